// round 7
// baseline (speedup 1.0000x reference)
#include <cuda_runtime.h>
#include <math_constants.h>

// Sparse segment-max pooling, CSR two-pass, vectorized gather.
//   features : [N_IN, 32] f32, in_map : [E] i32, out_map : [E] i32 sorted,
//   out : [N_OUT, 32] f32 (empty segments -> 0)
//
// Pass B layout: one warp per output row. Lane l covers row-group g = l>>3
// and columns c4 = (l&7)*4 .. +3 (float4). One batch of <=32 edges is fetched
// with a single coalesced in_map load; the 8 group-iterations are fully
// unrolled and predicated, so up to 32 feature rows (4 KB) are in flight per
// warp via LDG.128. Cross-group max via shfl_xor(8,16); 8 lanes store one
// coalesced 128B float4 row.

#define MAX_NOUT (1 << 18)

__device__ int g_offsets[MAX_NOUT + 1];

__global__ __launch_bounds__(256)
void build_offsets(const int* __restrict__ out_map, int E, int n_out)
{
    int e = blockIdx.x * blockDim.x + threadIdx.x;
    if (e >= E) return;

    int o = __ldg(&out_map[e]);
    if (o < 0) o = 0;
    if (o >= n_out) o = n_out - 1;

    // prev via warp shuffle: one coalesced load instead of two.
    int prev = __shfl_up_sync(0xffffffffu, o, 1);
    if ((threadIdx.x & 31) == 0)
        prev = (e == 0) ? -1 : min(max(__ldg(&out_map[e - 1]), 0), n_out - 1);

    for (int r = prev + 1; r <= o; r++)
        g_offsets[r] = e;

    if (e == E - 1)
        for (int r = o + 1; r <= n_out; r++)
            g_offsets[r] = E;
}

__device__ __forceinline__ float4 f4max(float4 a, float4 b) {
    return make_float4(fmaxf(a.x, b.x), fmaxf(a.y, b.y),
                       fmaxf(a.z, b.z), fmaxf(a.w, b.w));
}

__global__ __launch_bounds__(256)
void sparse_pool_kernel(const float* __restrict__ features,
                        const int*   __restrict__ in_map,
                        float*       __restrict__ out,
                        int n_out)
{
    const int warp_global = (blockIdx.x * blockDim.x + threadIdx.x) >> 5;
    const int lane = threadIdx.x & 31;
    if (warp_global >= n_out) return;

    const int target = warp_global;
    const int g  = lane >> 3;        // row group 0..3
    const int c4 = (lane & 7) * 4;   // column base for this lane's float4

    const int start = __ldg(&g_offsets[target]);
    const int end   = __ldg(&g_offsets[target + 1]);

    const float NI = -CUDART_INF_F;
    float4 m = make_float4(NI, NI, NI, NI);

    for (int base = start; base < end; base += 32) {
        const int cnt = min(end - base, 32);

        // One coalesced load covers up to 32 edge indices.
        int myidx = (lane < cnt) ? __ldg(&in_map[base + lane]) : 0;

        // 8 fully-unrolled predicated group-iterations: lane's edge position
        // p = i*4 + g. All valid LDG.128s are independent -> up to 32 rows
        // (4KB) in flight per warp.
        #pragma unroll
        for (int i = 0; i < 8; i++) {
            const int p = i * 4 + g;
            const bool valid = (p < cnt);
            int r = __shfl_sync(0xffffffffu, myidx, p & 31);
            if (valid) {
                float4 f = *(const float4*)(features + (size_t)r * 32 + c4);
                m = f4max(m, f);
            }
        }
    }

    // Combine the 4 row-groups: lanes l, l^8, l^16, l^24 hold the same columns.
    #pragma unroll
    for (int d = 8; d <= 16; d <<= 1) {
        float4 t;
        t.x = __shfl_xor_sync(0xffffffffu, m.x, d);
        t.y = __shfl_xor_sync(0xffffffffu, m.y, d);
        t.z = __shfl_xor_sync(0xffffffffu, m.z, d);
        t.w = __shfl_xor_sync(0xffffffffu, m.w, d);
        m = f4max(m, t);
    }

    // Empty segment -> 0 (reference maps -inf to 0).
    if (end <= start) m = make_float4(0.f, 0.f, 0.f, 0.f);

    // Lanes 0..7 store one coalesced 128B row.
    if (lane < 8)
        *(float4*)(out + (size_t)target * 32 + c4) = m;
}

extern "C" void kernel_launch(void* const* d_in, const int* in_sizes, int n_in,
                              void* d_out, int out_size)
{
    const float* features = (const float*)d_in[0];
    const int*   in_map   = (const int*)d_in[1];
    const int*   out_map  = (const int*)d_in[2];
    float* out = (float*)d_out;

    const int E = in_sizes[1];
    int n_out = out_size / 32;
    if (n_out > MAX_NOUT) n_out = MAX_NOUT;

    {
        const int threads = 256;
        const int blocks = (E + threads - 1) / threads;
        build_offsets<<<blocks, threads>>>(out_map, E, n_out);
    }
    {
        const int threads = 256;  // 8 warps/block
        const int blocks = (n_out * 32 + threads - 1) / threads;
        sparse_pool_kernel<<<blocks, threads>>>(features, in_map, out, n_out);
    }
}